// round 7
// baseline (speedup 1.0000x reference)
#include <cuda_runtime.h>
#include <cuda_bf16.h>

// BiLSTM persistent kernel. 256 CTAs x 256 threads (2 CTAs/SM -> 16 warps/SM).
// Gates tile 32(M) x 128(N) per CTA; fc tile 32x32 on 64 CTAs per dir.
// FFMA2 inner loop, float4 smem traffic, mov.b64 packing (as in passing R4).

#define T_STEPS 255
#define BATCH   256
#define HID     512
#define VEC     256
#define G4H     2048
#define NCTA    256u

__device__ float g_wihR[2][2][G4H][VEC];   // [dir][depth][4j+g][k]
__device__ float g_whhR[2][2][G4H][HID];
__device__ float g_biasR[2][2][G4H];
__device__ float g_h[2][2][2][BATCH][HID]; // [parity][dir][depth][b][j]
__device__ float g_c[2][2][BATCH][HID];
__device__ float g_v[2][BATCH][VEC];
__device__ unsigned g_count;
__device__ unsigned g_gen;

// ---- packed f32x2 helpers --------------------------------------------------
__device__ __forceinline__ unsigned long long pk2(float x, float y)
{
    unsigned long long r;
    asm("mov.b64 %0, {%1, %2};" : "=l"(r) : "f"(x), "f"(y));
    return r;
}
__device__ __forceinline__ void fma2(unsigned long long& d,
                                     unsigned long long a, unsigned long long b)
{
    asm("fma.rn.f32x2 %0, %1, %2, %0;" : "+l"(d) : "l"(a), "l"(b));
}
__device__ __forceinline__ void upk2(float& lo, float& hi, unsigned long long v)
{
    asm("mov.b64 {%0, %1}, %2;" : "=f"(lo), "=f"(hi) : "l"(v));
}

// ---------------------------------------------------------------------------
__global__ void prep_kernel(const float* __restrict__ wih_l, const float* __restrict__ whh_l,
                            const float* __restrict__ bih_l, const float* __restrict__ bhh_l,
                            const float* __restrict__ wih_r, const float* __restrict__ whh_r,
                            const float* __restrict__ bih_r, const float* __restrict__ bhh_r)
{
    const unsigned tid = blockIdx.x * blockDim.x + threadIdx.x;
    const unsigned nth = gridDim.x * blockDim.x;
    if (tid == 0) { g_count = 0u; g_gen = 0u; }

    for (unsigned i = tid; i < (1u << 21); i += nth) {     // wihR
        unsigned k  = i & 255u;
        unsigned r  = (i >> 8) & 2047u;
        unsigned d  = (i >> 19) & 1u;
        unsigned dr = (i >> 20) & 1u;
        unsigned j = r >> 2, g = r & 3u;
        const float* src = dr ? wih_r : wih_l;
        ((float*)g_wihR)[i] = src[((size_t)d * G4H + g * HID + j) * VEC + k];
    }
    for (unsigned i = tid; i < (1u << 22); i += nth) {     // whhR
        unsigned k  = i & 511u;
        unsigned r  = (i >> 9) & 2047u;
        unsigned d  = (i >> 20) & 1u;
        unsigned dr = (i >> 21) & 1u;
        unsigned j = r >> 2, g = r & 3u;
        const float* src = dr ? whh_r : whh_l;
        ((float*)g_whhR)[i] = src[((size_t)d * G4H + g * HID + j) * HID + k];
    }
    for (unsigned i = tid; i < 8192u; i += nth) {          // biasR
        unsigned r  = i & 2047u;
        unsigned d  = (i >> 11) & 1u;
        unsigned dr = (i >> 12) & 1u;
        unsigned j = r >> 2, g = r & 3u;
        const float* bi = dr ? bih_r : bih_l;
        const float* bh = dr ? bhh_r : bhh_l;
        ((float*)g_biasR)[i] = bi[d * G4H + g * HID + j] + bh[d * G4H + g * HID + j];
    }
    for (unsigned i = tid; i < 524288u; i += nth) {        // h parity-0, c
        ((float*)g_h)[i] = 0.f;
        ((float*)g_c)[i] = 0.f;
    }
}

// ---------------------------------------------------------------------------
__device__ __forceinline__ void grid_bar(unsigned* s_gen)
{
    __syncthreads();
    if (threadIdx.x == 0) {
        unsigned my = ++(*s_gen);
        __threadfence();
        if (atomicAdd(&g_count, 1u) == NCTA - 1u) {
            g_count = 0u;
            __threadfence();
            atomicAdd(&g_gen, 1u);
        } else {
            while (*((volatile unsigned*)&g_gen) < my) { __nanosleep(32); }
        }
        __threadfence();
    }
    __syncthreads();
}

// ---------------------------------------------------------------------------
// Gates tile: 32(M) x 128(N), 256 threads, thread tile 4 rows x 4 cols.
// Thread's 4 cols = one hidden unit's (i,f,g,o).
// ---------------------------------------------------------------------------
__device__ __forceinline__ void do_gates(
    float* __restrict__ sA, float* __restrict__ sB, int tid,
    const float* __restrict__ xin, long lda0,
    const float* __restrict__ wih, const float* __restrict__ whh,
    const float* __restrict__ bias,
    const float* __restrict__ hin, float* __restrict__ hout,
    float* __restrict__ cst, int bm, int bn)
{
    const int rg4 = (tid >> 5) << 2;   // warp-uniform row base 0..28 (8 warps)
    const int cg4 = (tid & 31) << 2;   // col base 0..124

    unsigned long long acc[2][4];      // [rowpair][col]
#pragma unroll
    for (int i = 0; i < 2; i++)
#pragma unroll
        for (int j = 0; j < 4; j++) acc[i][j] = 0ull;

    float4 pa, pb[4];
    const int ar = tid >> 3, akq = (tid & 7) << 2;   // A: 256 float4, 1/thread

#pragma unroll
    for (int seg = 0; seg < 2; ++seg) {
        const float* A   = seg ? hin : xin;
        const long  lda  = seg ? (long)HID : lda0;
        const float* Bw  = seg ? whh : wih;
        const int   ldb  = seg ? HID : VEC;
        const int   Ks   = seg ? HID : VEC;

        pa = *(const float4*)(A + (long)(bm + ar) * lda + akq);
#pragma unroll
        for (int i = 0; i < 4; ++i) {
            int f = tid + (i << 8); int n = f >> 3; int kq = (f & 7) << 2;
            pb[i] = *(const float4*)(Bw + (long)(bn + n) * ldb + kq);
        }

        for (int k0 = 0; k0 < Ks; k0 += 32) {
            __syncthreads();
            sA[(akq + 0) * 68 + ar] = pa.x; sA[(akq + 1) * 68 + ar] = pa.y;
            sA[(akq + 2) * 68 + ar] = pa.z; sA[(akq + 3) * 68 + ar] = pa.w;
#pragma unroll
            for (int i = 0; i < 4; ++i) {
                int f = tid + (i << 8); int n = f >> 3; int kq = (f & 7) << 2;
                sB[(kq + 0) * 136 + n] = pb[i].x; sB[(kq + 1) * 136 + n] = pb[i].y;
                sB[(kq + 2) * 136 + n] = pb[i].z; sB[(kq + 3) * 136 + n] = pb[i].w;
            }
            __syncthreads();

            int kn = k0 + 32;
            if (kn < Ks) {
                pa = *(const float4*)(A + (long)(bm + ar) * lda + kn + akq);
#pragma unroll
                for (int i = 0; i < 4; ++i) {
                    int f = tid + (i << 8); int n = f >> 3; int kq = (f & 7) << 2;
                    pb[i] = *(const float4*)(Bw + (long)(bn + n) * ldb + kn + kq);
                }
            }

#pragma unroll
            for (int kk = 0; kk < 32; ++kk) {
                float4 a0 = *(const float4*)&sA[kk * 68 + rg4];   // rows rg4..+3
                float4 b0 = *(const float4*)&sB[kk * 136 + cg4];  // cols cg4..+3

                unsigned long long ap0 = pk2(a0.x, a0.y);
                unsigned long long ap1 = pk2(a0.z, a0.w);
                unsigned long long bb0 = pk2(b0.x, b0.x);
                unsigned long long bb1 = pk2(b0.y, b0.y);
                unsigned long long bb2 = pk2(b0.z, b0.z);
                unsigned long long bb3 = pk2(b0.w, b0.w);

                fma2(acc[0][0], ap0, bb0); fma2(acc[0][1], ap0, bb1);
                fma2(acc[0][2], ap0, bb2); fma2(acc[0][3], ap0, bb3);
                fma2(acc[1][0], ap1, bb0); fma2(acc[1][1], ap1, bb1);
                fma2(acc[1][2], ap1, bb2); fma2(acc[1][3], ap1, bb3);
            }
        }
    }

    // Epilogue: 4 cols = (i,f,g,o) of unit u; rows rg4..rg4+3.
    const int u   = (bn + cg4) >> 2;
    const float bi0 = bias[bn + cg4 + 0];
    const float bi1 = bias[bn + cg4 + 1];
    const float bi2 = bias[bn + cg4 + 2];
    const float bi3 = bias[bn + cg4 + 3];
#pragma unroll
    for (int rp = 0; rp < 2; ++rp) {
        float glo[4], ghi[4];
        upk2(glo[0], ghi[0], acc[rp][0]);
        upk2(glo[1], ghi[1], acc[rp][1]);
        upk2(glo[2], ghi[2], acc[rp][2]);
        upk2(glo[3], ghi[3], acc[rp][3]);
#pragma unroll
        for (int hf = 0; hf < 2; ++hf) {
            const float* gv = hf ? ghi : glo;
            int m = bm + rg4 + 2 * rp + hf;
            long idx = (long)m * HID + u;
            float ig = gv[0] + bi0;
            float fg = gv[1] + bi1;
            float gg = gv[2] + bi2;
            float og = gv[3] + bi3;
            float c_old = cst[idx];
            float si = 1.f / (1.f + __expf(-ig));
            float sf = 1.f / (1.f + __expf(-fg));
            float so = 1.f / (1.f + __expf(-og));
            float tg = tanhf(gg);
            float cn = sf * c_old + si * tg;
            cst[idx]  = cn;
            hout[idx] = so * tanhf(cn);
        }
    }
}

// ---------------------------------------------------------------------------
// FC tile: 32(M) x 32(N), K=512. 256 threads, thread tile 2x2 (R4-identical).
// ---------------------------------------------------------------------------
__device__ __forceinline__ void do_fc(
    float* __restrict__ sA, float* __restrict__ sB, int tid,
    const float* __restrict__ hin, const float* __restrict__ Wf,
    const float* __restrict__ bf,
    float* __restrict__ outp, long ldo, int bm, int bn)
{
    const int r2 = (tid >> 4) << 1;
    const int c2 = (tid & 15) << 1;
    float acc00 = 0.f, acc01 = 0.f, acc10 = 0.f, acc11 = 0.f;

    const int r = tid >> 3; const int kq = (tid & 7) << 2;
    float4 pa = *(const float4*)(hin + (long)(bm + r) * HID + kq);
    float4 pb = *(const float4*)(Wf + (long)(bn + r) * HID + kq);

    for (int k0 = 0; k0 < HID; k0 += 32) {
        __syncthreads();
        sA[(kq + 0) * 68 + r] = pa.x; sA[(kq + 1) * 68 + r] = pa.y;
        sA[(kq + 2) * 68 + r] = pa.z; sA[(kq + 3) * 68 + r] = pa.w;
        sB[(kq + 0) * 136 + r] = pb.x; sB[(kq + 1) * 136 + r] = pb.y;
        sB[(kq + 2) * 136 + r] = pb.z; sB[(kq + 3) * 136 + r] = pb.w;
        __syncthreads();

        int kn = k0 + 32;
        if (kn < HID) {
            pa = *(const float4*)(hin + (long)(bm + r) * HID + kn + kq);
            pb = *(const float4*)(Wf + (long)(bn + r) * HID + kn + kq);
        }

#pragma unroll
        for (int kk = 0; kk < 32; ++kk) {
            float a0 = sA[kk * 68 + r2], a1 = sA[kk * 68 + r2 + 1];
            float b0 = sB[kk * 136 + c2], b1 = sB[kk * 136 + c2 + 1];
            acc00 = fmaf(a0, b0, acc00); acc01 = fmaf(a0, b1, acc01);
            acc10 = fmaf(a1, b0, acc10); acc11 = fmaf(a1, b1, acc11);
        }
    }

    float bfx = bf[bn + c2], bfy = bf[bn + c2 + 1];
    *(float2*)(outp + (long)(bm + r2) * ldo + bn + c2)     = make_float2(acc00 + bfx, acc01 + bfy);
    *(float2*)(outp + (long)(bm + r2 + 1) * ldo + bn + c2) = make_float2(acc10 + bfx, acc11 + bfy);
}

// ---------------------------------------------------------------------------
// Persistent kernel: 256 CTAs (2/SM), 4 grid barriers per step.
// ---------------------------------------------------------------------------
__global__ __launch_bounds__(256, 2) void bilstm_kernel(
    const float* __restrict__ x,
    const float* __restrict__ wfc_l, const float* __restrict__ wfc_r,
    const float* __restrict__ bfc_l, const float* __restrict__ bfc_r,
    float* __restrict__ out)
{
    __shared__ float sA[32 * 68];
    __shared__ float sB[32 * 136];
    __shared__ unsigned s_gen;

    const int tid = threadIdx.x;
    const int cid = blockIdx.x;
    const int dir = cid >> 7;          // 0..1
    const int idx = cid & 127;         // 0..127
    const int gbm = (idx >> 4) << 5;   // gates M tile (32): 8 tiles
    const int gbn = (idx & 15) << 7;   // gates N tile (128): 16 tiles
    const bool fc_on = (idx < 64);
    const int fbm = (idx >> 3) << 5;   // fc M tile (32): 8 tiles (idx<64)
    const int fbn = (idx & 7) << 5;    // fc N tile (32): 8 tiles

    if (tid == 0) s_gen = 0u;
    __syncthreads();

    const float* wfc = dir ? wfc_r : wfc_l;
    const float* bfc = dir ? bfc_r : bfc_l;

    for (int t = 0; t < T_STEPS; ++t) {
        const int p = t & 1;

        {   // gates depth 0
            int step = dir ? (T_STEPS - t) : t;
            do_gates(sA, sB, tid, x + (long)step * VEC, (long)256 * VEC,
                     &g_wihR[dir][0][0][0], &g_whhR[dir][0][0][0],
                     &g_biasR[dir][0][0],
                     &g_h[p][dir][0][0][0], &g_h[p ^ 1][dir][0][0][0],
                     &g_c[dir][0][0][0], gbm, gbn);
        }
        grid_bar(&s_gen);

        if (fc_on)
            do_fc(sA, sB, tid, &g_h[p ^ 1][dir][0][0][0], wfc, bfc,
                  &g_v[dir][0][0], VEC, fbm, fbn);
        grid_bar(&s_gen);

        do_gates(sA, sB, tid, &g_v[dir][0][0], (long)VEC,
                 &g_wihR[dir][1][0][0], &g_whhR[dir][1][0][0],
                 &g_biasR[dir][1][0],
                 &g_h[p][dir][1][0][0], &g_h[p ^ 1][dir][1][0][0],
                 &g_c[dir][1][0][0], gbm, gbn);
        grid_bar(&s_gen);

        if (fc_on) {   // fc depth 1 -> output
            int tout = dir ? (T_STEPS + t) : t;
            do_fc(sA, sB, tid, &g_h[p ^ 1][dir][1][0][0],
                  wfc + (long)VEC * HID, bfc + VEC,
                  out + (long)tout * VEC, (long)2 * T_STEPS * VEC, fbm, fbn);
        }
        grid_bar(&s_gen);
    }
}

// ---------------------------------------------------------------------------
extern "C" void kernel_launch(void* const* d_in, const int* in_sizes, int n_in,
                              void* d_out, int out_size)
{
    const float* x     = (const float*)d_in[0];
    const float* wih_l = (const float*)d_in[1];
    const float* whh_l = (const float*)d_in[2];
    const float* bih_l = (const float*)d_in[3];
    const float* bhh_l = (const float*)d_in[4];
    const float* wfc_l = (const float*)d_in[5];
    const float* bfc_l = (const float*)d_in[6];
    const float* wih_r = (const float*)d_in[7];
    const float* whh_r = (const float*)d_in[8];
    const float* bih_r = (const float*)d_in[9];
    const float* bhh_r = (const float*)d_in[10];
    const float* wfc_r = (const float*)d_in[11];
    const float* bfc_r = (const float*)d_in[12];
    float* out = (float*)d_out;

    prep_kernel<<<256, 256>>>(wih_l, whh_l, bih_l, bhh_l,
                              wih_r, whh_r, bih_r, bhh_r);
    bilstm_kernel<<<NCTA, 256>>>(x, wfc_l, wfc_r, bfc_l, bfc_r, out);
}

// round 8
// speedup vs baseline: 1.4997x; 1.4997x over previous
#include <cuda_runtime.h>
#include <cuda_bf16.h>

// BiLSTM persistent-kernel, f32x2 (FFMA2) gates inner loop.
// 128 CTAs x 256 threads (one wave), software grid barriers, 2-node graph.
// R8: u64 A-operand loads from smem (kills 4 movs/kk), launch_bounds(256,1)
// to unlock the full 256-reg budget for pipelining. Otherwise identical to R4.

#define T_STEPS 255
#define BATCH   256
#define HID     512
#define VEC     256
#define G4H     2048
#define NCTA    128u

__device__ float g_wihR[2][2][G4H][VEC];   // [dir][depth][4j+g][k]
__device__ float g_whhR[2][2][G4H][HID];
__device__ float g_biasR[2][2][G4H];
__device__ float g_h[2][2][2][BATCH][HID]; // [parity][dir][depth][b][j]
__device__ float g_c[2][2][BATCH][HID];
__device__ float g_v[2][BATCH][VEC];
__device__ unsigned g_count;
__device__ unsigned g_gen;

// ---- packed f32x2 helpers --------------------------------------------------
__device__ __forceinline__ unsigned long long pk2(float x, float y)
{
    unsigned long long r;
    asm("mov.b64 %0, {%1, %2};" : "=l"(r) : "f"(x), "f"(y));
    return r;
}
__device__ __forceinline__ void fma2(unsigned long long& d,
                                     unsigned long long a, unsigned long long b)
{
    asm("fma.rn.f32x2 %0, %1, %2, %0;" : "+l"(d) : "l"(a), "l"(b));
}
__device__ __forceinline__ void upk2(float& lo, float& hi, unsigned long long v)
{
    asm("mov.b64 {%0, %1}, %2;" : "=f"(lo), "=f"(hi) : "l"(v));
}

// ---------------------------------------------------------------------------
__global__ void prep_kernel(const float* __restrict__ wih_l, const float* __restrict__ whh_l,
                            const float* __restrict__ bih_l, const float* __restrict__ bhh_l,
                            const float* __restrict__ wih_r, const float* __restrict__ whh_r,
                            const float* __restrict__ bih_r, const float* __restrict__ bhh_r)
{
    const unsigned tid = blockIdx.x * blockDim.x + threadIdx.x;
    const unsigned nth = gridDim.x * blockDim.x;
    if (tid == 0) { g_count = 0u; g_gen = 0u; }

    for (unsigned i = tid; i < (1u << 21); i += nth) {     // wihR
        unsigned k  = i & 255u;
        unsigned r  = (i >> 8) & 2047u;
        unsigned d  = (i >> 19) & 1u;
        unsigned dr = (i >> 20) & 1u;
        unsigned j = r >> 2, g = r & 3u;
        const float* src = dr ? wih_r : wih_l;
        ((float*)g_wihR)[i] = src[((size_t)d * G4H + g * HID + j) * VEC + k];
    }
    for (unsigned i = tid; i < (1u << 22); i += nth) {     // whhR
        unsigned k  = i & 511u;
        unsigned r  = (i >> 9) & 2047u;
        unsigned d  = (i >> 20) & 1u;
        unsigned dr = (i >> 21) & 1u;
        unsigned j = r >> 2, g = r & 3u;
        const float* src = dr ? whh_r : whh_l;
        ((float*)g_whhR)[i] = src[((size_t)d * G4H + g * HID + j) * HID + k];
    }
    for (unsigned i = tid; i < 8192u; i += nth) {          // biasR
        unsigned r  = i & 2047u;
        unsigned d  = (i >> 11) & 1u;
        unsigned dr = (i >> 12) & 1u;
        unsigned j = r >> 2, g = r & 3u;
        const float* bi = dr ? bih_r : bih_l;
        const float* bh = dr ? bhh_r : bhh_l;
        ((float*)g_biasR)[i] = bi[d * G4H + g * HID + j] + bh[d * G4H + g * HID + j];
    }
    for (unsigned i = tid; i < 524288u; i += nth) {        // h parity-0, c
        ((float*)g_h)[i] = 0.f;
        ((float*)g_c)[i] = 0.f;
    }
}

// ---------------------------------------------------------------------------
__device__ __forceinline__ void grid_bar(unsigned* s_gen)
{
    __syncthreads();
    if (threadIdx.x == 0) {
        unsigned my = ++(*s_gen);
        __threadfence();
        if (atomicAdd(&g_count, 1u) == NCTA - 1u) {
            g_count = 0u;
            __threadfence();
            atomicAdd(&g_gen, 1u);
        } else {
            while (*((volatile unsigned*)&g_gen) < my) { __nanosleep(32); }
        }
        __threadfence();
    }
    __syncthreads();
}

// ---------------------------------------------------------------------------
// Gates tile: 64(M) x 128(N), 256 threads, thread tile 8 rows x 4 cols.
// Thread's 4 cols = one hidden unit's (i,f,g,o).
// A row-pairs read directly as packed u64 from smem (adjacent in [k][row]).
// ---------------------------------------------------------------------------
__device__ __forceinline__ void do_gates(
    float* __restrict__ sA, float* __restrict__ sB, int tid,
    const float* __restrict__ xin, long lda0,
    const float* __restrict__ wih, const float* __restrict__ whh,
    const float* __restrict__ bias,
    const float* __restrict__ hin, float* __restrict__ hout,
    float* __restrict__ cst, int bm, int bn)
{
    const int rg8 = (tid >> 5) << 3;   // warp-uniform row base 0..56
    const int cg4 = (tid & 31) << 2;   // col base 0..124

    unsigned long long acc[4][4];      // [rowpair][col]
#pragma unroll
    for (int i = 0; i < 4; i++)
#pragma unroll
        for (int j = 0; j < 4; j++) acc[i][j] = 0ull;

    float4 pa[2], pb[4];

#pragma unroll
    for (int seg = 0; seg < 2; ++seg) {
        const float* A   = seg ? hin : xin;
        const long  lda  = seg ? (long)HID : lda0;
        const float* Bw  = seg ? whh : wih;
        const int   ldb  = seg ? HID : VEC;
        const int   Ks   = seg ? HID : VEC;

#pragma unroll
        for (int i = 0; i < 2; ++i) {
            int f = tid + (i << 8); int r = f >> 3; int kq = (f & 7) << 2;
            pa[i] = *(const float4*)(A + (long)(bm + r) * lda + kq);
        }
#pragma unroll
        for (int i = 0; i < 4; ++i) {
            int f = tid + (i << 8); int n = f >> 3; int kq = (f & 7) << 2;
            pb[i] = *(const float4*)(Bw + (long)(bn + n) * ldb + kq);
        }

        for (int k0 = 0; k0 < Ks; k0 += 32) {
            __syncthreads();
#pragma unroll
            for (int i = 0; i < 2; ++i) {
                int f = tid + (i << 8); int r = f >> 3; int kq = (f & 7) << 2;
                sA[(kq + 0) * 68 + r] = pa[i].x; sA[(kq + 1) * 68 + r] = pa[i].y;
                sA[(kq + 2) * 68 + r] = pa[i].z; sA[(kq + 3) * 68 + r] = pa[i].w;
            }
#pragma unroll
            for (int i = 0; i < 4; ++i) {
                int f = tid + (i << 8); int n = f >> 3; int kq = (f & 7) << 2;
                sB[(kq + 0) * 136 + n] = pb[i].x; sB[(kq + 1) * 136 + n] = pb[i].y;
                sB[(kq + 2) * 136 + n] = pb[i].z; sB[(kq + 3) * 136 + n] = pb[i].w;
            }
            __syncthreads();

            int kn = k0 + 32;
            if (kn < Ks) {
#pragma unroll
                for (int i = 0; i < 2; ++i) {
                    int f = tid + (i << 8); int r = f >> 3; int kq = (f & 7) << 2;
                    pa[i] = *(const float4*)(A + (long)(bm + r) * lda + kn + kq);
                }
#pragma unroll
                for (int i = 0; i < 4; ++i) {
                    int f = tid + (i << 8); int n = f >> 3; int kq = (f & 7) << 2;
                    pb[i] = *(const float4*)(Bw + (long)(bn + n) * ldb + kn + kq);
                }
            }

#pragma unroll
            for (int kk = 0; kk < 32; ++kk) {
                // A: rows rg8..rg8+7 as 4 packed f32x2 pairs, no mov.b64 needed.
                // Alignment: (kk*68 + rg8) and (+4) are multiples of 4 floats.
                const ulonglong2 apA = *(const ulonglong2*)&sA[kk * 68 + rg8];
                const ulonglong2 apB = *(const ulonglong2*)&sA[kk * 68 + rg8 + 4];
                const float4 b0 = *(const float4*)&sB[kk * 136 + cg4];

                unsigned long long bb0 = pk2(b0.x, b0.x);
                unsigned long long bb1 = pk2(b0.y, b0.y);
                unsigned long long bb2 = pk2(b0.z, b0.z);
                unsigned long long bb3 = pk2(b0.w, b0.w);

                fma2(acc[0][0], apA.x, bb0); fma2(acc[0][1], apA.x, bb1);
                fma2(acc[0][2], apA.x, bb2); fma2(acc[0][3], apA.x, bb3);
                fma2(acc[1][0], apA.y, bb0); fma2(acc[1][1], apA.y, bb1);
                fma2(acc[1][2], apA.y, bb2); fma2(acc[1][3], apA.y, bb3);
                fma2(acc[2][0], apB.x, bb0); fma2(acc[2][1], apB.x, bb1);
                fma2(acc[2][2], apB.x, bb2); fma2(acc[2][3], apB.x, bb3);
                fma2(acc[3][0], apB.y, bb0); fma2(acc[3][1], apB.y, bb1);
                fma2(acc[3][2], apB.y, bb2); fma2(acc[3][3], apB.y, bb3);
            }
        }
    }

    // Epilogue: thread's 4 cols = (i,f,g,o) of hidden unit u, 8 rows.
    const int u  = (bn + cg4) >> 2;
    const float bi0 = bias[bn + cg4 + 0];
    const float bi1 = bias[bn + cg4 + 1];
    const float bi2 = bias[bn + cg4 + 2];
    const float bi3 = bias[bn + cg4 + 3];
#pragma unroll
    for (int rp = 0; rp < 4; ++rp) {
        float glo[4], ghi[4];
        upk2(glo[0], ghi[0], acc[rp][0]);
        upk2(glo[1], ghi[1], acc[rp][1]);
        upk2(glo[2], ghi[2], acc[rp][2]);
        upk2(glo[3], ghi[3], acc[rp][3]);
#pragma unroll
        for (int hf = 0; hf < 2; ++hf) {
            const float* gv = hf ? ghi : glo;
            int m = bm + rg8 + 2 * rp + hf;
            long idx = (long)m * HID + u;
            float ig = gv[0] + bi0;
            float fg = gv[1] + bi1;
            float gg = gv[2] + bi2;
            float og = gv[3] + bi3;
            float c_old = cst[idx];
            float si = 1.f / (1.f + __expf(-ig));
            float sf = 1.f / (1.f + __expf(-fg));
            float so = 1.f / (1.f + __expf(-og));
            float tg = tanhf(gg);
            float cn = sf * c_old + si * tg;
            cst[idx]  = cn;
            hout[idx] = so * tanhf(cn);
        }
    }
}

// ---------------------------------------------------------------------------
// FC tile: 32(M) x 32(N), K=512. 256 threads, thread tile 2x2 (R4-identical).
// ---------------------------------------------------------------------------
__device__ __forceinline__ void do_fc(
    float* __restrict__ sA, float* __restrict__ sB, int tid,
    const float* __restrict__ hin, const float* __restrict__ Wf,
    const float* __restrict__ bf,
    float* __restrict__ outp, long ldo, int bm, int bn)
{
    const int r2 = (tid >> 4) << 1;
    const int c2 = (tid & 15) << 1;
    float acc00 = 0.f, acc01 = 0.f, acc10 = 0.f, acc11 = 0.f;

    const int r = tid >> 3; const int kq = (tid & 7) << 2;
    float4 pa = *(const float4*)(hin + (long)(bm + r) * HID + kq);
    float4 pb = *(const float4*)(Wf + (long)(bn + r) * HID + kq);

    for (int k0 = 0; k0 < HID; k0 += 32) {
        __syncthreads();
        sA[(kq + 0) * 68 + r] = pa.x; sA[(kq + 1) * 68 + r] = pa.y;
        sA[(kq + 2) * 68 + r] = pa.z; sA[(kq + 3) * 68 + r] = pa.w;
        sB[(kq + 0) * 136 + r] = pb.x; sB[(kq + 1) * 136 + r] = pb.y;
        sB[(kq + 2) * 136 + r] = pb.z; sB[(kq + 3) * 136 + r] = pb.w;
        __syncthreads();

        int kn = k0 + 32;
        if (kn < HID) {
            pa = *(const float4*)(hin + (long)(bm + r) * HID + kn + kq);
            pb = *(const float4*)(Wf + (long)(bn + r) * HID + kn + kq);
        }

#pragma unroll
        for (int kk = 0; kk < 32; ++kk) {
            float a0 = sA[kk * 68 + r2], a1 = sA[kk * 68 + r2 + 1];
            float b0 = sB[kk * 136 + c2], b1 = sB[kk * 136 + c2 + 1];
            acc00 = fmaf(a0, b0, acc00); acc01 = fmaf(a0, b1, acc01);
            acc10 = fmaf(a1, b0, acc10); acc11 = fmaf(a1, b1, acc11);
        }
    }

    float bfx = bf[bn + c2], bfy = bf[bn + c2 + 1];
    *(float2*)(outp + (long)(bm + r2) * ldo + bn + c2)     = make_float2(acc00 + bfx, acc01 + bfy);
    *(float2*)(outp + (long)(bm + r2 + 1) * ldo + bn + c2) = make_float2(acc10 + bfx, acc11 + bfy);
}

// ---------------------------------------------------------------------------
// Persistent kernel: all 255 steps, 3 grid barriers per step.
// ---------------------------------------------------------------------------
__global__ __launch_bounds__(256, 1) void bilstm_kernel(
    const float* __restrict__ x,
    const float* __restrict__ wfc_l, const float* __restrict__ wfc_r,
    const float* __restrict__ bfc_l, const float* __restrict__ bfc_r,
    float* __restrict__ out)
{
    __shared__ float sA[32 * 68];
    __shared__ float sB[32 * 136];
    __shared__ unsigned s_gen;

    const int tid = threadIdx.x;
    const int cid = blockIdx.x;
    const int dir = cid >> 6;
    const int idx = cid & 63;
    const int gbm = (idx >> 4) << 6;   // gates M tile (64)
    const int gbn = (idx & 15) << 7;   // gates N tile (128)
    const int fbm = (idx >> 3) << 5;   // fc M tile (32)
    const int fbn = (idx & 7) << 5;    // fc N tile (32)

    if (tid == 0) s_gen = 0u;
    __syncthreads();

    const float* wfc = dir ? wfc_r : wfc_l;
    const float* bfc = dir ? bfc_r : bfc_l;

    for (int t = 0; t < T_STEPS; ++t) {
        const int p = t & 1;

        {   // gates depth 0 (input = x at step)
            int step = dir ? (T_STEPS - t) : t;
            do_gates(sA, sB, tid, x + (long)step * VEC, (long)256 * VEC,
                     &g_wihR[dir][0][0][0], &g_whhR[dir][0][0][0],
                     &g_biasR[dir][0][0],
                     &g_h[p][dir][0][0][0], &g_h[p ^ 1][dir][0][0][0],
                     &g_c[dir][0][0][0], gbm, gbn);
        }
        grid_bar(&s_gen);

        do_fc(sA, sB, tid, &g_h[p ^ 1][dir][0][0][0], wfc, bfc,
              &g_v[dir][0][0], VEC, fbm, fbn);
        grid_bar(&s_gen);

        do_gates(sA, sB, tid, &g_v[dir][0][0], (long)VEC,
                 &g_wihR[dir][1][0][0], &g_whhR[dir][1][0][0],
                 &g_biasR[dir][1][0],
                 &g_h[p][dir][1][0][0], &g_h[p ^ 1][dir][1][0][0],
                 &g_c[dir][1][0][0], gbm, gbn);
        grid_bar(&s_gen);

        {   // fc depth 1 -> output
            int tout = dir ? (T_STEPS + t) : t;
            do_fc(sA, sB, tid, &g_h[p ^ 1][dir][1][0][0],
                  wfc + (long)VEC * HID, bfc + VEC,
                  out + (long)tout * VEC, (long)2 * T_STEPS * VEC, fbm, fbn);
        }
        // no barrier: gates0(t+1) is independent of fc1(t); the barrier after
        // gates0(t+1) orders everything downstream.
    }
}

// ---------------------------------------------------------------------------
extern "C" void kernel_launch(void* const* d_in, const int* in_sizes, int n_in,
                              void* d_out, int out_size)
{
    const float* x     = (const float*)d_in[0];
    const float* wih_l = (const float*)d_in[1];
    const float* whh_l = (const float*)d_in[2];
    const float* bih_l = (const float*)d_in[3];
    const float* bhh_l = (const float*)d_in[4];
    const float* wfc_l = (const float*)d_in[5];
    const float* bfc_l = (const float*)d_in[6];
    const float* wih_r = (const float*)d_in[7];
    const float* whh_r = (const float*)d_in[8];
    const float* bih_r = (const float*)d_in[9];
    const float* bhh_r = (const float*)d_in[10];
    const float* wfc_r = (const float*)d_in[11];
    const float* bfc_r = (const float*)d_in[12];
    float* out = (float*)d_out;

    prep_kernel<<<256, 256>>>(wih_l, whh_l, bih_l, bhh_l,
                              wih_r, whh_r, bih_r, bhh_r);
    bilstm_kernel<<<NCTA, 256>>>(x, wfc_l, wfc_r, bfc_l, bfc_r, out);
}